// round 16
// baseline (speedup 1.0000x reference)
#include <cuda_runtime.h>
#include <cuda_fp16.h>
#include <math.h>
#include <stdint.h>

#define BATCH 4096
#define NVAR  16
#define DDIM  256
#define FEAT  4096
#define NELEM ((size_t)BATCH * FEAT)     // 16,777,216
#define VWN   ((size_t)NVAR * DDIM * DDIM)

// ---------------- scratch (device globals; allocation forbidden) -----------
__device__ __align__(256) __half g_gc[NELEM];    // concat GLU result g (fp16)
__device__ __align__(256) __half g_gv[NELEM];    // var GLU result gv (fp16)
// fp16 activations
__device__ __align__(256) __half g_xh[NELEM];
__device__ __align__(256) __half g_hh[NELEM];    // concat h
__device__ __align__(256) __half g_eh[NELEM];    // concat e1
__device__ __align__(256) __half g_hv[NELEM];    // var h
__device__ __align__(256) __half g_ev[NELEM];    // var e1
// transposed fp16 weights
__device__ __align__(256) __half g_cW2h[NELEM];
__device__ __align__(256) __half g_cW1h[NELEM];
__device__ __align__(256) __half g_cW45h[2 * NELEM];  // interleaved W4|W5
__device__ __align__(256) __half g_vW2h[VWN];
__device__ __align__(256) __half g_vW1h[VWN];
__device__ __align__(256) __half g_vW45h[2 * VWN];    // interleaved per var

// ---------------- helpers ---------------------------------------------------
__device__ __forceinline__ uint32_t smem_u32(const void* p) {
    uint32_t a;
    asm("{ .reg .u64 t; cvta.to.shared.u64 t, %1; cvt.u32.u64 %0, t; }"
        : "=r"(a) : "l"(p));
    return a;
}

#define CP_ASYNC16(dst, src) \
    asm volatile("cp.async.cg.shared.global [%0], [%1], 16;" :: "r"(dst), "l"(src))
#define CP_COMMIT() asm volatile("cp.async.commit_group;" ::: "memory")
#define CP_WAIT3()  asm volatile("cp.async.wait_group 3;" ::: "memory")

#define LDSM4(r, a) \
    asm volatile("ldmatrix.sync.aligned.m8n8.x4.shared.b16 {%0,%1,%2,%3}, [%4];" \
                 : "=r"((r)[0]), "=r"((r)[1]), "=r"((r)[2]), "=r"((r)[3]) : "r"(a))

__device__ __forceinline__ void mma16816(float* d, const uint32_t* a,
                                         uint32_t b0, uint32_t b1) {
    asm volatile(
        "mma.sync.aligned.m16n8k16.row.col.f32.f16.f16.f32 "
        "{%0,%1,%2,%3}, {%4,%5,%6,%7}, {%8,%9}, {%0,%1,%2,%3};"
        : "+f"(d[0]), "+f"(d[1]), "+f"(d[2]), "+f"(d[3])
        : "r"(a[0]), "r"(a[1]), "r"(a[2]), "r"(a[3]), "r"(b0), "r"(b1));
}

// ---------------- merged GEMM (mma.sync fp16) — R13 schedule ---------------
#define BM 128
#define BN 128
#define BK 32
#define ROWB 80
#define A_BYTES (BM * ROWB)
#define B_BYTES (BN * ROWB)
#define STAGEB (A_BYTES + B_BYTES)
#define NSTAGE 5
#define GEMM_SMEM (NSTAGE * STAGEB)      // 102400

struct GDesc {
    const __half* A;
    const __half* B;
    const float*  bias;      // ACT 0/1: bias; ACT 2: bias of W4 (even cols)
    const float*  bias2;     // ACT 2: bias of W5 (odd cols)
    __half*       Ch;
    int  K, lda, ldb, ldc;
    long sAn, sBn, sBiasN, sCn;
    int  ntN, tilesPerZ;
};

__device__ __forceinline__ void load_chunk(
    uint32_t s0, int tid, int k0,
    const __half* __restrict__ Ah, int lda, int bm,
    const __half* __restrict__ Bh, int ldb, int bn)
{
#pragma unroll
    for (int r = 0; r < 2; r++) {
        int e = tid + r * 256;
        int row = e >> 2, seg = e & 3;
        CP_ASYNC16(s0 + (uint32_t)row * ROWB + seg * 16,
                   Ah + (size_t)(bm + row) * lda + k0 + seg * 8);
    }
#pragma unroll
    for (int r = 0; r < 2; r++) {
        int e = tid + r * 256;
        int row = e >> 2, seg = e & 3;
        CP_ASYNC16(s0 + A_BYTES + (uint32_t)row * ROWB + seg * 16,
                   Bh + (size_t)(bn + row) * ldb + k0 + seg * 8);
    }
}

// ACT: 0 none, 1 ELU, 2 fused GLU on interleaved W4|W5 columns.
template <int ACT>
__global__ __launch_bounds__(256, 2)
void mgemm_k(GDesc c0, GDesc c1, int tiles0)
{
    extern __shared__ char smem[];
    const uint32_t sbase = smem_u32(smem);
    const int tid = threadIdx.x;
    const int bx = blockIdx.x;

    GDesc d;
    int nb, tm, tn;
    if (bx < tiles0) {
        d = c0; nb = 0;
        tm = bx / d.ntN; tn = bx % d.ntN;
    } else {
        d = c1;
        int v = bx - tiles0;
        nb = v / d.tilesPerZ;
        int rem = v % d.tilesPerZ;
        tm = rem / d.ntN; tn = rem % d.ntN;
    }
    const __half* Ah = d.A + (size_t)nb * d.sAn;
    const __half* Bh = d.B + (size_t)nb * d.sBn;
    const float* bias  = d.bias  + (size_t)nb * d.sBiasN;
    const float* bias2 = (ACT == 2) ? d.bias2 + (size_t)nb * d.sBiasN : nullptr;
    const size_t coff = (size_t)nb * d.sCn;
    const int lda = d.lda, ldb = d.ldb, ldc = d.ldc, K = d.K;
    const int bm = tm * BM, bn = tn * BN;

    const int lane = tid & 31, wid = tid >> 5;
    const int wm = wid & 1, wn = wid >> 1;       // 2(m) x 4(n)
    const int lr = lane & 15, lc = lane >> 4;

    float acc[4][4][4];
#pragma unroll
    for (int a = 0; a < 4; a++)
#pragma unroll
        for (int b = 0; b < 4; b++)
#pragma unroll
            for (int c = 0; c < 4; c++) acc[a][b][c] = 0.f;

    const int nk = K / BK;
#pragma unroll
    for (int j = 0; j < 4; j++) {
        if (j < nk)
            load_chunk(sbase + j * STAGEB, tid, j * BK, Ah, lda, bm, Bh, ldb, bn);
        CP_COMMIT();
    }

    int stR = 0, stW = 4;
    for (int i = 0; i < nk; i++) {
        CP_WAIT3();
        __syncthreads();
        const uint32_t sb = sbase + (uint32_t)stR * STAGEB;
        const uint32_t raBase = sb + (uint32_t)(wm * 64 + lr) * ROWB;
        const uint32_t rbBase = sb + A_BYTES + (uint32_t)(wn * 32 + lr) * ROWB;

#pragma unroll
        for (int ks = 0; ks < 2; ks++) {
            const uint32_t koff = (uint32_t)(ks * 16 + lc * 8) * 2;
            uint32_t ah[4][4];
#pragma unroll
            for (int mt = 0; mt < 4; mt++)
                LDSM4(ah[mt], raBase + (uint32_t)(mt * 16) * ROWB + koff);
#pragma unroll
            for (int nt = 0; nt < 2; nt++) {
                uint32_t bh[4];
                LDSM4(bh, rbBase + (uint32_t)(nt * 16) * ROWB + koff);
#pragma unroll
                for (int mt = 0; mt < 4; mt++) {
                    mma16816(acc[mt][nt * 2 + 0], ah[mt], bh[0], bh[2]);
                    mma16816(acc[mt][nt * 2 + 1], ah[mt], bh[1], bh[3]);
                }
            }
        }

        int j = i + 4;
        if (j < nk)
            load_chunk(sbase + (uint32_t)stW * STAGEB, tid, j * BK,
                       Ah, lda, bm, Bh, ldb, bn);
        CP_COMMIT();
        stR = (stR + 1 == NSTAGE) ? 0 : stR + 1;
        stW = (stW + 1 == NSTAGE) ? 0 : stW + 1;
    }

    // Epilogue: warp tile 64x32.
    const int rbase = bm + wm * 64 + (lane >> 2);
    const int cbase = bn + wn * 32 + (lane & 3) * 2;
#pragma unroll
    for (int mt = 0; mt < 4; mt++) {
#pragma unroll
        for (int t8 = 0; t8 < 4; t8++) {
            const int r = rbase + mt * 16;
            const int c = cbase + t8 * 8;
            if (ACT == 2) {
                // even col = t4, odd col = t5; one GLU output per pair.
                const int cc = c >> 1;
                const float bb4 = bias[cc], bb5 = bias2[cc];
                float t40 = acc[mt][t8][0] + bb4;
                float t50 = acc[mt][t8][1] + bb5;
                float t41 = acc[mt][t8][2] + bb4;
                float t51 = acc[mt][t8][3] + bb5;
                float g0 = t50 * (1.f / (1.f + expf(-t40)));
                float g1 = t51 * (1.f / (1.f + expf(-t41)));
                d.Ch[coff + (size_t)r * ldc + cc] = __float2half_rn(g0);
                d.Ch[coff + (size_t)(r + 8) * ldc + cc] = __float2half_rn(g1);
            } else {
                const float b0 = bias[c], b1 = bias[c + 1];
                float v00 = acc[mt][t8][0] + b0, v01 = acc[mt][t8][1] + b1;
                float v10 = acc[mt][t8][2] + b0, v11 = acc[mt][t8][3] + b1;
                if (ACT == 1) {
                    v00 = v00 > 0.f ? v00 : expm1f(v00);
                    v01 = v01 > 0.f ? v01 : expm1f(v01);
                    v10 = v10 > 0.f ? v10 : expm1f(v10);
                    v11 = v11 > 0.f ? v11 : expm1f(v11);
                }
                __half2 H0 = __floats2half2_rn(v00, v01);
                __half2 H1 = __floats2half2_rn(v10, v11);
                *(uint32_t*)(d.Ch + coff + (size_t)r * ldc + c) =
                    *reinterpret_cast<uint32_t*>(&H0);
                *(uint32_t*)(d.Ch + coff + (size_t)(r + 8) * ldc + c) =
                    *reinterpret_cast<uint32_t*>(&H1);
            }
        }
    }
}

// ---------------- convert fp32 -> fp16 -------------------------------------
__global__ __launch_bounds__(256)
void cvt16_k(const float* __restrict__ src, __half* __restrict__ dst, size_t n)
{
    size_t i = ((size_t)blockIdx.x * blockDim.x + threadIdx.x) * 4;
    if (i >= n) return;
    float4 v = *(const float4*)(src + i);
    __half2 h0 = __floats2half2_rn(v.x, v.y);
    __half2 h1 = __floats2half2_rn(v.z, v.w);
    uint2 o = { *reinterpret_cast<uint32_t*>(&h0), *reinterpret_cast<uint32_t*>(&h1) };
    *(uint2*)((unsigned short*)dst + i) = o;
}

// ---------------- transpose + convert, 2 plain weights ---------------------
__global__ __launch_bounds__(256)
void tcvt2_k(const float* __restrict__ s0, const float* __restrict__ s1,
             __half* __restrict__ d0, __half* __restrict__ d1,
             int K, int Ncol, int zPerW)
{
    __shared__ float t[64][33];
    int w = blockIdx.z / zPerW;
    int z = blockIdx.z % zPerW;
    const float* src = (w == 0 ? s0 : s1) + (size_t)z * K * Ncol;
    __half* dst = (w == 0 ? d0 : d1) + (size_t)z * K * Ncol;
    int k0 = blockIdx.y * 64, n0 = blockIdx.x * 32;
#pragma unroll
    for (int r = 0; r < 8; r++)
        t[threadIdx.y + 8 * r][threadIdx.x] =
            src[(size_t)(k0 + threadIdx.y + 8 * r) * Ncol + n0 + threadIdx.x];
    __syncthreads();
#pragma unroll
    for (int r = 0; r < 4; r++) {
        int n = threadIdx.y + 8 * r;
        int kk = threadIdx.x;
        __half2 h = __floats2half2_rn(t[2 * kk][n], t[2 * kk + 1][n]);
        *(__half2*)(dst + (size_t)(n0 + n) * K + k0 + 2 * kk) = h;
    }
}

// ---------------- transpose + convert, interleaved pair (W4,W5) ------------
// dst row 2n+w holds column n of weight w.
__global__ __launch_bounds__(256)
void tcvt2i_k(const float* __restrict__ s0, const float* __restrict__ s1,
              __half* __restrict__ dst0, int K, int Ncol, int zPerW)
{
    __shared__ float t[64][33];
    int w = blockIdx.z / zPerW;
    int z = blockIdx.z % zPerW;
    const float* src = (w == 0 ? s0 : s1) + (size_t)z * K * Ncol;
    __half* dst = dst0 + (size_t)z * 2 * K * Ncol;
    int k0 = blockIdx.y * 64, n0 = blockIdx.x * 32;
#pragma unroll
    for (int r = 0; r < 8; r++)
        t[threadIdx.y + 8 * r][threadIdx.x] =
            src[(size_t)(k0 + threadIdx.y + 8 * r) * Ncol + n0 + threadIdx.x];
    __syncthreads();
#pragma unroll
    for (int r = 0; r < 4; r++) {
        int n = threadIdx.y + 8 * r;
        int kk = threadIdx.x;
        __half2 h = __floats2half2_rn(t[2 * kk][n], t[2 * kk + 1][n]);
        *(__half2*)(dst + (size_t)(2 * (n0 + n) + w) * K + k0 + 2 * kk) = h;
    }
}

// ---------------- fused LN(4096)+softmax + per-(b,n) LN(256)+combine -------
__global__ __launch_bounds__(256)
void final_k(const float* __restrict__ x, const __half* __restrict__ g,
             const float* __restrict__ gamma, const float* __restrict__ beta,
             const __half* __restrict__ gv, const float* __restrict__ vlng,
             const float* __restrict__ vlnb, float* __restrict__ out)
{
    __shared__ float s[FEAT];
    __shared__ float xs[FEAT];
    __shared__ float red[8];
    __shared__ float part[8][DDIM];
    const int b = blockIdx.x, t = threadIdx.x;
    const int lane = t & 31, wrp = t >> 5;
    const float* xb = x + (size_t)b * FEAT;
    const __half* gb = g + (size_t)b * FEAT;

    float lsum = 0.f;
    for (int i = t; i < FEAT; i += 256) {
        float xv = xb[i];
        xs[i] = xv;
        float v = xv + __half2float(gb[i]);
        s[i] = v; lsum += v;
    }
#pragma unroll
    for (int o = 16; o; o >>= 1) lsum += __shfl_xor_sync(0xffffffff, lsum, o);
    if (lane == 0) red[wrp] = lsum;
    __syncthreads();
    float tot = 0.f;
#pragma unroll
    for (int i = 0; i < 8; i++) tot += red[i];
    float mean = tot * (1.f / FEAT);
    __syncthreads();

    float lvar = 0.f;
    for (int i = t; i < FEAT; i += 256) { float dd = s[i] - mean; lvar += dd * dd; }
#pragma unroll
    for (int o = 16; o; o >>= 1) lvar += __shfl_xor_sync(0xffffffff, lvar, o);
    if (lane == 0) red[wrp] = lvar;
    __syncthreads();
    float vtot = 0.f;
#pragma unroll
    for (int i = 0; i < 8; i++) vtot += red[i];
    float rstd = rsqrtf(vtot * (1.f / FEAT) + 1e-5f);

    for (int i = t; i < FEAT; i += 256)
        s[i] = (s[i] - mean) * rstd * gamma[i] + beta[i];
    __syncthreads();

    {
        float c[NVAR];
        float m = -1e30f;
#pragma unroll
        for (int n = 0; n < NVAR; n++) { c[n] = s[n * DDIM + t]; m = fmaxf(m, c[n]); }
        float sum = 0.f;
#pragma unroll
        for (int n = 0; n < NVAR; n++) { c[n] = expf(c[n] - m); sum += c[n]; }
        float inv = 1.f / sum;
#pragma unroll
        for (int n = 0; n < NVAR; n++) s[n * DDIM + t] = c[n] * inv;
    }
    __syncthreads();

    float accl[8];
#pragma unroll
    for (int j = 0; j < 8; j++) accl[j] = 0.f;

#pragma unroll
    for (int nn = 0; nn < 2; nn++) {
        const int n = wrp * 2 + nn;
        const int lbase = n * DDIM;
        const size_t gbase = (size_t)b * FEAT + lbase;
        float v[8];
        float sum = 0.f;
#pragma unroll
        for (int j = 0; j < 8; j++) {
            v[j] = xs[lbase + lane + 32 * j] +
                   __half2float(gv[gbase + lane + 32 * j]);
            sum += v[j];
        }
#pragma unroll
        for (int o = 16; o; o >>= 1) sum += __shfl_xor_sync(0xffffffff, sum, o);
        const float meanl = sum * (1.f / DDIM);
        float var = 0.f;
#pragma unroll
        for (int j = 0; j < 8; j++) { float dl = v[j] - meanl; var += dl * dl; }
#pragma unroll
        for (int o = 16; o; o >>= 1) var += __shfl_xor_sync(0xffffffff, var, o);
        const float rstdl = rsqrtf(var * (1.f / DDIM) + 1e-5f);
#pragma unroll
        for (int j = 0; j < 8; j++) {
            const int dcol = lane + 32 * j;
            float yv = (v[j] - meanl) * rstdl * vlng[lbase + dcol]
                       + vlnb[lbase + dcol];
            accl[j] += s[lbase + dcol] * yv;
        }
    }
#pragma unroll
    for (int j = 0; j < 8; j++) part[wrp][lane + 32 * j] = accl[j];
    __syncthreads();
    float sm = 0.f;
#pragma unroll
    for (int k = 0; k < 8; k++) sm += part[k][t];
    out[(size_t)b * DDIM + t] = sm;
}

// ---------------- launch ----------------------------------------------------
extern "C" void kernel_launch(void* const* d_in, const int* in_sizes, int n_in,
                              void* d_out, int out_size)
{
    const float* x    = (const float*)d_in[0];
    const float* vW2  = (const float*)d_in[1];
    const float* vb2  = (const float*)d_in[2];
    const float* vW1  = (const float*)d_in[3];
    const float* vb1  = (const float*)d_in[4];
    const float* vW4  = (const float*)d_in[5];
    const float* vb4  = (const float*)d_in[6];
    const float* vW5  = (const float*)d_in[7];
    const float* vb5  = (const float*)d_in[8];
    const float* vlng = (const float*)d_in[9];
    const float* vlnb = (const float*)d_in[10];
    const float* cW2  = (const float*)d_in[11];
    const float* cb2  = (const float*)d_in[12];
    const float* cW1  = (const float*)d_in[13];
    const float* cb1  = (const float*)d_in[14];
    const float* cW4  = (const float*)d_in[15];
    const float* cb4  = (const float*)d_in[16];
    const float* cW5  = (const float*)d_in[17];
    const float* cb5  = (const float*)d_in[18];
    const float* clng = (const float*)d_in[19];
    const float* clnb = (const float*)d_in[20];
    float* out = (float*)d_out;

    __half *gc, *gv;
    cudaGetSymbolAddress((void**)&gc, g_gc);
    cudaGetSymbolAddress((void**)&gv, g_gv);
    __half *xh, *hh, *eh, *hv, *ev;
    cudaGetSymbolAddress((void**)&xh, g_xh);
    cudaGetSymbolAddress((void**)&hh, g_hh);
    cudaGetSymbolAddress((void**)&eh, g_eh);
    cudaGetSymbolAddress((void**)&hv, g_hv);
    cudaGetSymbolAddress((void**)&ev, g_ev);
    __half *cW2h, *cW1h, *cW45h;
    cudaGetSymbolAddress((void**)&cW2h, g_cW2h);
    cudaGetSymbolAddress((void**)&cW1h, g_cW1h);
    cudaGetSymbolAddress((void**)&cW45h, g_cW45h);
    __half *vW2h, *vW1h, *vW45h;
    cudaGetSymbolAddress((void**)&vW2h, g_vW2h);
    cudaGetSymbolAddress((void**)&vW1h, g_vW1h);
    cudaGetSymbolAddress((void**)&vW45h, g_vW45h);

    cudaFuncSetAttribute(mgemm_k<1>, cudaFuncAttributeMaxDynamicSharedMemorySize, GEMM_SMEM);
    cudaFuncSetAttribute(mgemm_k<0>, cudaFuncAttributeMaxDynamicSharedMemorySize, GEMM_SMEM);
    cudaFuncSetAttribute(mgemm_k<2>, cudaFuncAttributeMaxDynamicSharedMemorySize, GEMM_SMEM);

    const size_t NE = NELEM;

    // ---- conversions ----
    cvt16_k<<<(unsigned)(NE / 1024), 256>>>(x, xh, NE);
    {
        dim3 b(32, 8);
        dim3 gc2(FEAT / 32, FEAT / 64, 2);
        tcvt2_k<<<gc2, b>>>(cW2, cW1, cW2h, cW1h, FEAT, FEAT, 1);
        tcvt2i_k<<<gc2, b>>>(cW4, cW5, cW45h, FEAT, FEAT, 1);
        dim3 gv2(DDIM / 32, DDIM / 64, 2 * NVAR);
        tcvt2_k<<<gv2, b>>>(vW2, vW1, vW2h, vW1h, DDIM, DDIM, NVAR);
        tcvt2i_k<<<gv2, b>>>(vW4, vW5, vW45h, DDIM, DDIM, NVAR);
    }

    // ---- descriptor templates ----
    const int ccTiles  = (FEAT / BN) * (BATCH / BM);      // 1024
    const int vTilesZ  = (DDIM / BN) * (BATCH / BM);      // 64
    const int vTiles   = vTilesZ * NVAR;                  // 1024
    const unsigned totalTiles = ccTiles + vTiles;         // 2048
    const int ccTilesM = (2 * FEAT / BN) * (BATCH / BM);  // 2048 (merged)
    const int vTilesZM = (2 * DDIM / BN) * (BATCH / BM);  // 128
    const unsigned totalTilesM = ccTilesM + vTilesZM * NVAR;  // 4096

    auto mkC = [&](const __half* A, const __half* B, const float* bias,
                   const float* bias2, __half* ch, int ntn, int tpz) {
        GDesc d;
        d.A = A; d.B = B; d.bias = bias; d.bias2 = bias2; d.Ch = ch;
        d.K = FEAT; d.lda = FEAT; d.ldb = FEAT; d.ldc = FEAT;
        d.sAn = 0; d.sBn = 0; d.sBiasN = 0; d.sCn = 0;
        d.ntN = ntn; d.tilesPerZ = tpz;
        return d;
    };
    auto mkV = [&](const __half* A, const __half* B, const float* bias,
                   const float* bias2, __half* ch, int ntn, int tpz, long sbn) {
        GDesc d;
        d.A = A; d.B = B; d.bias = bias; d.bias2 = bias2; d.Ch = ch;
        d.K = DDIM; d.lda = FEAT; d.ldb = DDIM; d.ldc = FEAT;
        d.sAn = DDIM; d.sBn = sbn; d.sBiasN = DDIM; d.sCn = DDIM;
        d.ntN = ntn; d.tilesPerZ = tpz;
        return d;
    };

    // ---- merged GEMM launches ----
    // L1: h = elu(x@W2+b2)  -> hh / hv
    mgemm_k<1><<<totalTiles, 256, GEMM_SMEM>>>(
        mkC(xh, cW2h, cb2, nullptr, hh, FEAT / BN, ccTiles),
        mkV(xh, vW2h, vb2, nullptr, hv, DDIM / BN, vTilesZ, (long)DDIM * DDIM),
        ccTiles);
    // L2: e1 = h@W1+b1      -> eh / ev
    mgemm_k<0><<<totalTiles, 256, GEMM_SMEM>>>(
        mkC(hh, cW1h, cb1, nullptr, eh, FEAT / BN, ccTiles),
        mkV(hv, vW1h, vb1, nullptr, ev, DDIM / BN, vTilesZ, (long)DDIM * DDIM),
        ccTiles);
    // L3 merged: g = sigmoid(e1@W4+b4) * (e1@W5+b5)  -> gc / gv (fp16)
    mgemm_k<2><<<totalTilesM, 256, GEMM_SMEM>>>(
        mkC(eh, cW45h, cb4, cb5, gc, 2 * FEAT / BN, ccTilesM),
        mkV(ev, vW45h, vb4, vb5, gv, 2 * DDIM / BN, vTilesZM,
            (long)2 * DDIM * DDIM),
        ccTilesM);

    // ---- fused LN+softmax+combine ----
    final_k<<<BATCH, 256>>>(x, gc, clng, clnb, gv, vlng, vlnb, out);
}